// round 3
// baseline (speedup 1.0000x reference)
#include <cuda_runtime.h>

static constexpr int MAX_NC = 50000;
static constexpr int MAX_NG = 3000;
static constexpr int D      = 64;
static constexpr int EPT    = 4;   // edges per 16-lane group (one int4 of indices)

// Scratch: weighted source features (wf = feat * cj * mask).
__device__ float g_wf_c[MAX_NC * D];      // cells, weighted for 'exp'
__device__ float g_wf_grev[MAX_NG * D];   // genes, weighted for 'reverse-exp'
__device__ float g_wf_ggg[MAX_NG * D];    // genes, weighted for 'co-exp'
// Scratch: raw segment-sum accumulators (ci scaling deferred to epilogue).
__device__ float g_acc_c[MAX_NC * D];     // cell accumulator
__device__ float g_acc_gexp[MAX_NG * D];  // gene accumulator, 'exp'
__device__ float g_acc_ggg[MAX_NG * D];   // gene accumulator, 'co-exp'

// ---------------------------------------------------------------------------
// wf = feat * (cj * mask), one weighting.
// ---------------------------------------------------------------------------
__global__ void weight_rows1(const float* __restrict__ feat,
                             const float* __restrict__ cj,
                             const float* __restrict__ mask,
                             float* __restrict__ out, int n_vec) {
    int i = blockIdx.x * blockDim.x + threadIdx.x;
    if (i >= n_vec) return;
    int row = i >> 4;                       // 16 float4 per 64-float row
    float w = __ldg(cj + row) * __ldg(mask + row);
    float4 v = __ldg(((const float4*)feat) + i);
    v.x *= w; v.y *= w; v.z *= w; v.w *= w;
    ((float4*)out)[i] = v;
}

// Two weightings of the gene table in one pass.
__global__ void weight_rows2(const float* __restrict__ feat,
                             const float* __restrict__ cj1, const float* __restrict__ m1,
                             const float* __restrict__ cj2, const float* __restrict__ m2,
                             float* __restrict__ out1, float* __restrict__ out2,
                             int n_vec) {
    int i = blockIdx.x * blockDim.x + threadIdx.x;
    if (i >= n_vec) return;
    int row = i >> 4;
    float4 v = __ldg(((const float4*)feat) + i);
    float w1 = __ldg(cj1 + row) * __ldg(m1 + row);
    float w2 = __ldg(cj2 + row) * __ldg(m2 + row);
    ((float4*)out1)[i] = make_float4(v.x * w1, v.y * w1, v.z * w1, v.w * w1);
    ((float4*)out2)[i] = make_float4(v.x * w2, v.y * w2, v.z * w2, v.w * w2);
}

// ---------------------------------------------------------------------------
// Edge scatter, raw segment sum (no per-edge scaling).
// 16-lane group handles 4 consecutive edges; indices come in as one broadcast
// int4 per array (1 L1 wavefront each instead of 4). Each lane owns one float4
// slot of the 64-float row. acc[dst] += wf[src].
// ---------------------------------------------------------------------------
__global__ void edge_scatter4(const int* __restrict__ src,
                              const int* __restrict__ dst,
                              const float* __restrict__ wf,
                              float* __restrict__ acc,
                              int nE) {
    unsigned t = blockIdx.x * blockDim.x + threadIdx.x;
    int group = (int)(t >> 4);
    int lane  = (int)(t & 15u);
    int e0 = group * EPT;
    if (e0 >= nE) return;

    if (e0 + EPT <= nE) {
        // full group: vector index loads (broadcast within group)
        int4 s4 = __ldg((const int4*)(src + e0));
        int4 d4 = __ldg((const int4*)(dst + e0));
        int s[EPT] = {s4.x, s4.y, s4.z, s4.w};
        int d[EPT] = {d4.x, d4.y, d4.z, d4.w};

        float4 v[EPT];
        #pragma unroll
        for (int k = 0; k < EPT; k++)
            v[k] = __ldg((const float4*)(wf + (size_t)s[k] * D) + lane);

        #pragma unroll
        for (int k = 0; k < EPT; k++) {
            float* p = acc + (size_t)d[k] * D + lane * 4;
            asm volatile("red.global.add.v4.f32 [%0], {%1,%2,%3,%4};"
                         :: "l"(p), "f"(v[k].x), "f"(v[k].y), "f"(v[k].z), "f"(v[k].w)
                         : "memory");
        }
    } else {
        // tail group: scalar path
        for (int e = e0; e < nE; e++) {
            int s = __ldg(src + e);
            int d = __ldg(dst + e);
            float4 v = __ldg((const float4*)(wf + (size_t)s * D) + lane);
            float* p = acc + (size_t)d * D + lane * 4;
            asm volatile("red.global.add.v4.f32 [%0], {%1,%2,%3,%4};"
                         :: "l"(p), "f"(v.x), "f"(v.y), "f"(v.z), "f"(v.w)
                         : "memory");
        }
    }
}

// ---------------------------------------------------------------------------
// Epilogues: apply per-destination ci scaling (and alpha combine for genes).
// c_out = acc_c * ci_cell ; g_out = 0.5*(acc_gexp*ci_gene + acc_ggg*cii_gene)
// ---------------------------------------------------------------------------
__global__ void epilogue_c(const float* __restrict__ acc,
                           const float* __restrict__ ci,
                           float* __restrict__ out, int n_vec) {
    int i = blockIdx.x * blockDim.x + threadIdx.x;
    if (i >= n_vec) return;
    int row = i >> 4;
    float w = __ldg(ci + row);
    float4 v = ((const float4*)acc)[i];
    ((float4*)out)[i] = make_float4(v.x * w, v.y * w, v.z * w, v.w * w);
}

__global__ void epilogue_g(const float* __restrict__ acc1,
                           const float* __restrict__ ci1,
                           const float* __restrict__ acc2,
                           const float* __restrict__ ci2,
                           float* __restrict__ out, int n_vec) {
    int i = blockIdx.x * blockDim.x + threadIdx.x;
    if (i >= n_vec) return;
    int row = i >> 4;
    float w1 = 0.5f * __ldg(ci1 + row);
    float w2 = 0.5f * __ldg(ci2 + row);
    float4 a = ((const float4*)acc1)[i];
    float4 b = ((const float4*)acc2)[i];
    ((float4*)out)[i] = make_float4(a.x * w1 + b.x * w2,
                                    a.y * w1 + b.y * w2,
                                    a.z * w1 + b.z * w2,
                                    a.w * w1 + b.w * w2);
}

// ---------------------------------------------------------------------------
// kernel_launch
// Inputs: c_feat, g_feat, cj_cell, ci_cell, cj_gene, ci_gene, cjj_gene,
//   cii_gene, mask_exp, mask_rev, mask_gg,
//   src_cg, dst_cg, src_gc, dst_gc, src_gg, dst_gg
// Output: concat(c_out [NC*D], g_out [NG*D]) float32.
// ---------------------------------------------------------------------------
extern "C" void kernel_launch(void* const* d_in, const int* in_sizes, int n_in,
                              void* d_out, int out_size) {
    const float* c_feat   = (const float*)d_in[0];
    const float* g_feat   = (const float*)d_in[1];
    const float* cj_cell  = (const float*)d_in[2];
    const float* ci_cell  = (const float*)d_in[3];
    const float* cj_gene  = (const float*)d_in[4];
    const float* ci_gene  = (const float*)d_in[5];
    const float* cjj_gene = (const float*)d_in[6];
    const float* cii_gene = (const float*)d_in[7];
    const float* mask_exp = (const float*)d_in[8];
    const float* mask_rev = (const float*)d_in[9];
    const float* mask_gg  = (const float*)d_in[10];
    const int*   src_cg   = (const int*)d_in[11];
    const int*   dst_cg   = (const int*)d_in[12];
    const int*   src_gc   = (const int*)d_in[13];
    const int*   dst_gc   = (const int*)d_in[14];
    const int*   src_gg   = (const int*)d_in[15];
    const int*   dst_gg   = (const int*)d_in[16];

    const int nc   = in_sizes[0] / D;
    const int ng   = in_sizes[1] / D;
    const int e_cg = in_sizes[11];
    const int e_gc = in_sizes[13];
    const int e_gg = in_sizes[15];

    float* c_out = (float*)d_out;                  // [nc, D]
    float* g_out = (float*)d_out + (size_t)nc * D; // [ng, D]

    float *wf_c, *wf_grev, *wf_ggg, *acc_c, *acc_gexp, *acc_ggg;
    cudaGetSymbolAddress((void**)&wf_c,     g_wf_c);
    cudaGetSymbolAddress((void**)&wf_grev,  g_wf_grev);
    cudaGetSymbolAddress((void**)&wf_ggg,   g_wf_ggg);
    cudaGetSymbolAddress((void**)&acc_c,    g_acc_c);
    cudaGetSymbolAddress((void**)&acc_gexp, g_acc_gexp);
    cudaGetSymbolAddress((void**)&acc_ggg,  g_acc_ggg);

    // 1) zero the scratch accumulators
    cudaMemsetAsync(acc_c,    0, (size_t)nc * D * sizeof(float));
    cudaMemsetAsync(acc_gexp, 0, (size_t)ng * D * sizeof(float));
    cudaMemsetAsync(acc_ggg,  0, (size_t)ng * D * sizeof(float));

    // 2) precompute weighted source features
    {
        int nv = nc * (D / 4);
        weight_rows1<<<(nv + 255) / 256, 256>>>(c_feat, cj_cell, mask_exp, wf_c, nv);
    }
    {
        int nv = ng * (D / 4);
        weight_rows2<<<(nv + 255) / 256, 256>>>(g_feat, cj_gene, mask_rev,
                                                cjj_gene, mask_gg,
                                                wf_grev, wf_ggg, nv);
    }

    // 3) raw segment-sum edge scatters
    auto launch_scatter = [](const int* s, const int* d, const float* wf,
                             float* acc, int nE) {
        long long groups = (nE + EPT - 1) / EPT;
        long long th = groups * 16;
        int blocks = (int)((th + 255) / 256);
        edge_scatter4<<<blocks, 256>>>(s, d, wf, acc, nE);
    };
    launch_scatter(src_cg, dst_cg, wf_c,    acc_gexp, e_cg);  // cell -> gene
    launch_scatter(src_gc, dst_gc, wf_grev, acc_c,    e_gc);  // gene -> cell
    launch_scatter(src_gg, dst_gg, wf_ggg,  acc_ggg,  e_gg);  // gene -> gene

    // 4) epilogues: per-destination ci scaling + alpha combine
    {
        int nv = nc * (D / 4);
        epilogue_c<<<(nv + 255) / 256, 256>>>(acc_c, ci_cell, c_out, nv);
    }
    {
        int nv = ng * (D / 4);
        epilogue_g<<<(nv + 255) / 256, 256>>>(acc_gexp, ci_gene,
                                              acc_ggg, cii_gene, g_out, nv);
    }
}

// round 4
// speedup vs baseline: 1.1251x; 1.1251x over previous
#include <cuda_runtime.h>
#include <cuda_fp16.h>

static constexpr int MAX_NC = 50000;
static constexpr int MAX_NG = 3000;
static constexpr int D      = 64;
static constexpr int EPT    = 4;   // edges per 16-lane group (one int4 of indices)

// Scratch: weighted source features in fp16 (wf = feat * cj * mask).
// Row = 64 halves = 128 bytes -> one L1 wavefront per edge gather.
__device__ __half g_wf_c[MAX_NC * D];      // cells, weighted for 'exp'
__device__ __half g_wf_grev[MAX_NG * D];   // genes, weighted for 'reverse-exp'
__device__ __half g_wf_ggg[MAX_NG * D];    // genes, weighted for 'co-exp'

// ---------------------------------------------------------------------------
// wf = fp16(feat * cj * mask), one weighting. One thread = one float4 = 4 vals.
// ---------------------------------------------------------------------------
__global__ void weight_rows1(const float* __restrict__ feat,
                             const float* __restrict__ cj,
                             const float* __restrict__ mask,
                             __half* __restrict__ out, int n_vec) {
    int i = blockIdx.x * blockDim.x + threadIdx.x;
    if (i >= n_vec) return;
    int row = i >> 4;                       // 16 float4 per 64-float row
    float w = __ldg(cj + row) * __ldg(mask + row);
    float4 v = __ldg(((const float4*)feat) + i);
    __half2 h0 = __floats2half2_rn(v.x * w, v.y * w);
    __half2 h1 = __floats2half2_rn(v.z * w, v.w * w);
    ((__half2*)out)[i * 2 + 0] = h0;
    ((__half2*)out)[i * 2 + 1] = h1;
}

// Two weightings of the gene table in one pass.
__global__ void weight_rows2(const float* __restrict__ feat,
                             const float* __restrict__ cj1, const float* __restrict__ m1,
                             const float* __restrict__ cj2, const float* __restrict__ m2,
                             __half* __restrict__ out1, __half* __restrict__ out2,
                             int n_vec) {
    int i = blockIdx.x * blockDim.x + threadIdx.x;
    if (i >= n_vec) return;
    int row = i >> 4;
    float4 v = __ldg(((const float4*)feat) + i);
    float w1 = __ldg(cj1 + row) * __ldg(m1 + row);
    float w2 = __ldg(cj2 + row) * __ldg(m2 + row);
    ((__half2*)out1)[i * 2 + 0] = __floats2half2_rn(v.x * w1, v.y * w1);
    ((__half2*)out1)[i * 2 + 1] = __floats2half2_rn(v.z * w1, v.w * w1);
    ((__half2*)out2)[i * 2 + 0] = __floats2half2_rn(v.x * w2, v.y * w2);
    ((__half2*)out2)[i * 2 + 1] = __floats2half2_rn(v.z * w2, v.w * w2);
}

// ---------------------------------------------------------------------------
// Edge scatter: out[dst] += alpha * ci[dst] * wf[src].
// 16-lane group handles EPT=4 consecutive edges (indices via one broadcast
// int4 each). Each lane gathers 4 halves (8 B) of the 128-B fp16 row, converts
// to f32, scales, and issues one red.global.add.v4.f32 (16 B).
// ---------------------------------------------------------------------------
__device__ __forceinline__ void scatter_one(const __half* __restrict__ wf,
                                            const float* __restrict__ ci,
                                            float* __restrict__ out,
                                            int s, int d, int lane, float alpha) {
    float scale = alpha * __ldg(ci + d);
    // 4 consecutive halves per lane: uint2 = 8 B; 16 lanes cover the 128-B row.
    uint2 raw = __ldg((const uint2*)(wf + (size_t)s * D) + lane);
    __half2 h0 = *reinterpret_cast<const __half2*>(&raw.x);
    __half2 h1 = *reinterpret_cast<const __half2*>(&raw.y);
    float2 f0 = __half22float2(h0);
    float2 f1 = __half22float2(h1);
    float4 r = make_float4(f0.x * scale, f0.y * scale, f1.x * scale, f1.y * scale);
    float* p = out + (size_t)d * D + lane * 4;
    asm volatile("red.global.add.v4.f32 [%0], {%1,%2,%3,%4};"
                 :: "l"(p), "f"(r.x), "f"(r.y), "f"(r.z), "f"(r.w)
                 : "memory");
}

__global__ void edge_scatter4(const int* __restrict__ src,
                              const int* __restrict__ dst,
                              const __half* __restrict__ wf,
                              const float* __restrict__ ci,
                              float* __restrict__ out,
                              int nE, float alpha) {
    unsigned t = blockIdx.x * blockDim.x + threadIdx.x;
    int group = (int)(t >> 4);
    int lane  = (int)(t & 15u);
    int e0 = group * EPT;
    if (e0 >= nE) return;

    if (e0 + EPT <= nE) {
        int4 s4 = __ldg((const int4*)(src + e0));
        int4 d4 = __ldg((const int4*)(dst + e0));
        int s[EPT] = {s4.x, s4.y, s4.z, s4.w};
        int d[EPT] = {d4.x, d4.y, d4.z, d4.w};

        // batch the long-latency loads for MLP, then scale+red
        float sc[EPT];
        uint2 raw[EPT];
        #pragma unroll
        for (int k = 0; k < EPT; k++) {
            sc[k]  = alpha * __ldg(ci + d[k]);
            raw[k] = __ldg((const uint2*)(wf + (size_t)s[k] * D) + lane);
        }
        #pragma unroll
        for (int k = 0; k < EPT; k++) {
            __half2 h0 = *reinterpret_cast<const __half2*>(&raw[k].x);
            __half2 h1 = *reinterpret_cast<const __half2*>(&raw[k].y);
            float2 f0 = __half22float2(h0);
            float2 f1 = __half22float2(h1);
            float4 r = make_float4(f0.x * sc[k], f0.y * sc[k],
                                   f1.x * sc[k], f1.y * sc[k]);
            float* p = out + (size_t)d[k] * D + lane * 4;
            asm volatile("red.global.add.v4.f32 [%0], {%1,%2,%3,%4};"
                         :: "l"(p), "f"(r.x), "f"(r.y), "f"(r.z), "f"(r.w)
                         : "memory");
        }
    } else {
        for (int e = e0; e < nE; e++)
            scatter_one(wf, ci, out, __ldg(src + e), __ldg(dst + e), lane, alpha);
    }
}

// ---------------------------------------------------------------------------
// kernel_launch
// Inputs: c_feat, g_feat, cj_cell, ci_cell, cj_gene, ci_gene, cjj_gene,
//   cii_gene, mask_exp, mask_rev, mask_gg,
//   src_cg, dst_cg, src_gc, dst_gc, src_gg, dst_gg
// Output: concat(c_out [NC*D], g_out [NG*D]) float32.
// ---------------------------------------------------------------------------
extern "C" void kernel_launch(void* const* d_in, const int* in_sizes, int n_in,
                              void* d_out, int out_size) {
    const float* c_feat   = (const float*)d_in[0];
    const float* g_feat   = (const float*)d_in[1];
    const float* cj_cell  = (const float*)d_in[2];
    const float* ci_cell  = (const float*)d_in[3];
    const float* cj_gene  = (const float*)d_in[4];
    const float* ci_gene  = (const float*)d_in[5];
    const float* cjj_gene = (const float*)d_in[6];
    const float* cii_gene = (const float*)d_in[7];
    const float* mask_exp = (const float*)d_in[8];
    const float* mask_rev = (const float*)d_in[9];
    const float* mask_gg  = (const float*)d_in[10];
    const int*   src_cg   = (const int*)d_in[11];
    const int*   dst_cg   = (const int*)d_in[12];
    const int*   src_gc   = (const int*)d_in[13];
    const int*   dst_gc   = (const int*)d_in[14];
    const int*   src_gg   = (const int*)d_in[15];
    const int*   dst_gg   = (const int*)d_in[16];

    const int nc   = in_sizes[0] / D;
    const int ng   = in_sizes[1] / D;
    const int e_cg = in_sizes[11];
    const int e_gc = in_sizes[13];
    const int e_gg = in_sizes[15];

    float* c_out = (float*)d_out;                  // [nc, D]
    float* g_out = (float*)d_out + (size_t)nc * D; // [ng, D]

    __half *wf_c, *wf_grev, *wf_ggg;
    cudaGetSymbolAddress((void**)&wf_c,    g_wf_c);
    cudaGetSymbolAddress((void**)&wf_grev, g_wf_grev);
    cudaGetSymbolAddress((void**)&wf_ggg,  g_wf_ggg);

    // 1) zero the output accumulators (poisoned to 0xAA by the harness)
    cudaMemsetAsync(d_out, 0, (size_t)out_size * sizeof(float));

    // 2) precompute fp16 weighted source features
    {
        int nv = nc * (D / 4);
        weight_rows1<<<(nv + 255) / 256, 256>>>(c_feat, cj_cell, mask_exp, wf_c, nv);
    }
    {
        int nv = ng * (D / 4);
        weight_rows2<<<(nv + 255) / 256, 256>>>(g_feat, cj_gene, mask_rev,
                                                cjj_gene, mask_gg,
                                                wf_grev, wf_ggg, nv);
    }

    // 3) edge scatters (ci and alpha folded into per-edge contribution)
    auto launch_scatter = [](const int* s, const int* d, const __half* wf,
                             const float* ci, float* out, int nE, float alpha) {
        long long groups = (nE + EPT - 1) / EPT;
        long long th = groups * 16;
        int blocks = (int)((th + 255) / 256);
        edge_scatter4<<<blocks, 256>>>(s, d, wf, ci, out, nE, alpha);
    };
    // cell -> gene ('exp'), alpha1 = 0.5
    launch_scatter(src_cg, dst_cg, wf_c, ci_gene, g_out, e_cg, 0.5f);
    // gene -> cell ('reverse-exp'), only relation into cells, alpha = 1
    launch_scatter(src_gc, dst_gc, wf_grev, ci_cell, c_out, e_gc, 1.0f);
    // gene -> gene ('co-exp'), (1 - alpha1) = 0.5
    launch_scatter(src_gg, dst_gg, wf_ggg, cii_gene, g_out, e_gg, 0.5f);
}